// round 1
// baseline (speedup 1.0000x reference)
#include <cuda_runtime.h>
#include <cstdint>
#include <cstddef>

#define NB 8192
#define NC 32000
#define ND 32

static constexpr int CS     = 25;            // class splits across grid.y
static constexpr int CPC    = NC / CS;       // 1280 classes per CTA
static constexpr int CHUNK  = 128;           // classes staged per smem chunk
static constexpr int NCHUNK = CPC / CHUNK;   // 10
static constexpr int RB     = 32;            // rows per CTA (lane == row)
static constexpr int NW     = 8;             // warps per CTA
static constexpr int WCH    = CHUNK / NW;    // 16 classes per warp per chunk
static constexpr int NBLK   = NB / RB;       // 256 row blocks

#define Y_MIN (1.0f + 1e-6f)

__device__ float g_S[NB];   // per-row sum of exp(-dist), accumulated via atomics

typedef unsigned long long ull;

__device__ __forceinline__ ull ffma2(ull a, ull b, ull c) {
    ull d; asm("fma.rn.f32x2 %0, %1, %2, %3;" : "=l"(d) : "l"(a), "l"(b), "l"(c)); return d;
}
__device__ __forceinline__ ull fmul2(ull a, ull b) {
    ull d; asm("mul.rn.f32x2 %0, %1, %2;" : "=l"(d) : "l"(a), "l"(b)); return d;
}
__device__ __forceinline__ ull fadd2(ull a, ull b) {
    ull d; asm("add.rn.f32x2 %0, %1, %2;" : "=l"(d) : "l"(a), "l"(b)); return d;
}
__device__ __forceinline__ ull pack2(float lo, float hi) {
    ull d; asm("mov.b64 %0, {%1, %2};" : "=l"(d) : "f"(lo), "f"(hi)); return d;
}
__device__ __forceinline__ float sum2(ull v) {
    float lo, hi; asm("mov.b64 {%0, %1}, %2;" : "=f"(lo), "=f"(hi) : "l"(v)); return lo + hi;
}
__device__ __forceinline__ float sqrt_approx(float x) {
    float r; asm("sqrt.approx.f32 %0, %1;" : "=f"(r) : "f"(x)); return r;
}
__device__ __forceinline__ uint32_t smem_u32(const void* p) {
    uint32_t r;
    asm("{ .reg .u64 t; cvta.to.shared.u64 t, %1; cvt.u32.u64 %0, t; }" : "=r"(r) : "l"(p));
    return r;
}
__device__ __forceinline__ void cp16(uint32_t dst, const void* src) {
    asm volatile("cp.async.cg.shared.global [%0], [%1], 16;" :: "r"(dst), "l"(src));
}

// ---------------- kernel 0: zero accumulators (runs every launch; graph-safe) --
__global__ void __launch_bounds__(256) k_zero(float* out) {
    int i = blockIdx.x * 256 + threadIdx.x;
    if (i < NB) g_S[i] = 0.0f;
    if (i == 0) out[0] = 0.0f;
}

// ---------------- kernel 1: fused Lorentz-dot + exp(-dist) row sums -----------
__global__ void __launch_bounds__(256) k_main(const float* __restrict__ pred,
                                              const float* __restrict__ embs) {
    __shared__ float cls[2][CHUNK * ND];   // double-buffered class chunk (2x16KB)
    __shared__ float red[NW][RB];

    const int tid  = threadIdx.x;
    const int w    = tid >> 5;
    const int lane = tid & 31;
    const int rb   = blockIdx.x;   // row block 0..255
    const int cs   = blockIdx.y;   // class split 0..24
    const int row  = rb * RB + lane;

    // Load this lane's pred row once; fold the Lorentz sign (y = p0*a0 - sum_{i>=1} p_i*a_i)
    ull pp[16];
    {
        const float4* pr = reinterpret_cast<const float4*>(pred + row * ND);
#pragma unroll
        for (int j = 0; j < 8; j++) {
            float4 v = pr[j];
            float a = (j == 0) ? v.x : -v.x;
            pp[2 * j]     = pack2(a,    -v.y);
            pp[2 * j + 1] = pack2(-v.z, -v.w);
        }
    }

    const char* cbase = reinterpret_cast<const char*>(embs)
                      + (size_t)cs * CPC * ND * sizeof(float);

    // stage chunk 0
    {
        uint32_t dst = smem_u32(&cls[0][0]);
#pragma unroll
        for (int i = 0; i < 4; i++) {
            int idx = tid + i * 256;                  // 1024 x 16B = 16KB, coalesced
            cp16(dst + idx * 16, cbase + idx * 16);
        }
        asm volatile("cp.async.commit_group;" ::: "memory");
    }

    float acc = 0.0f;
    int buf = 0;
#pragma unroll 1
    for (int ch = 0; ch < NCHUNK; ++ch) {
        if (ch + 1 < NCHUNK) {
            uint32_t dst = smem_u32(&cls[buf ^ 1][0]);
            const char* src = cbase + (size_t)(ch + 1) * CHUNK * ND * sizeof(float);
#pragma unroll
            for (int i = 0; i < 4; i++) {
                int idx = tid + i * 256;
                cp16(dst + idx * 16, src + idx * 16);
            }
            asm volatile("cp.async.commit_group;" ::: "memory");
            asm volatile("cp.async.wait_group 1;" ::: "memory");
        } else {
            asm volatile("cp.async.wait_group 0;" ::: "memory");
        }
        __syncthreads();

        const uint32_t cb = smem_u32(&cls[buf][(w * WCH) * ND]);
#pragma unroll 4
        for (int i = 0; i < WCH; i++) {
            ull s0, s1, s2, s3;
            // 32-float class vector, broadcast-LDS (all lanes same address)
            {
                ull c0, c1;
                asm("ld.shared.v2.u64 {%0,%1}, [%2];"
                    : "=l"(c0), "=l"(c1) : "r"(cb + i * (ND * 4) + 0));
                s0 = fmul2(c0, pp[0]); s1 = fmul2(c1, pp[1]);
                asm("ld.shared.v2.u64 {%0,%1}, [%2];"
                    : "=l"(c0), "=l"(c1) : "r"(cb + i * (ND * 4) + 16));
                s2 = fmul2(c0, pp[2]); s3 = fmul2(c1, pp[3]);
            }
#pragma unroll
            for (int j = 2; j < 8; j++) {
                ull c0, c1;
                asm("ld.shared.v2.u64 {%0,%1}, [%2];"
                    : "=l"(c0), "=l"(c1) : "r"(cb + i * (ND * 4) + j * 16));
                if ((j & 1) == 0) { s0 = ffma2(c0, pp[2 * j], s0); s1 = ffma2(c1, pp[2 * j + 1], s1); }
                else              { s2 = ffma2(c0, pp[2 * j], s2); s3 = ffma2(c1, pp[2 * j + 1], s3); }
            }
            float y = sum2(fadd2(fadd2(s0, s1), fadd2(s2, s3)));   // y = -<u,v>_L
            y = fmaxf(y, Y_MIN);
            float t = fmaf(y, y, -1.0f);
            acc += (y - sqrt_approx(t));        // exp(-arccosh(y)) = y - sqrt(y^2-1)
        }
        __syncthreads();
        buf ^= 1;
    }

    red[w][lane] = acc;
    __syncthreads();
    if (w == 0) {
        float t = 0.0f;
#pragma unroll
        for (int k = 0; k < NW; k++) t += red[k][lane];
        atomicAdd(&g_S[row], t);
    }
}

// ---------------- kernel 2: target distance + NLL mean ------------------------
__global__ void __launch_bounds__(256) k_fin(const float* __restrict__ pred,
                                             const int* __restrict__ tgt,
                                             const float* __restrict__ embs,
                                             float* __restrict__ out) {
    int r = blockIdx.x * 256 + threadIdx.x;   // grid 32 -> r < 8192 always
    int t = tgt[r];
    const float* pr = pred + r * ND;
    const float* ev = embs + (size_t)t * ND;

    float y = pr[0] * ev[0];
#pragma unroll
    for (int k = 1; k < ND; k++) y = fmaf(-pr[k], ev[k], y);
    y = fmaxf(y, Y_MIN);
    float dist = acoshf(y);
    float nll  = logf(g_S[r]) + dist;

#pragma unroll
    for (int o = 16; o; o >>= 1) nll += __shfl_down_sync(0xffffffffu, nll, o);

    __shared__ float sm[8];
    if ((threadIdx.x & 31) == 0) sm[threadIdx.x >> 5] = nll;
    __syncthreads();
    if (threadIdx.x == 0) {
        float s = 0.0f;
#pragma unroll
        for (int k = 0; k < 8; k++) s += sm[k];
        atomicAdd(out, s * (1.0f / NB));
    }
}

// ---------------- launch ------------------------------------------------------
extern "C" void kernel_launch(void* const* d_in, const int* in_sizes, int n_in,
                              void* d_out, int out_size) {
    const float* pred = (const float*)d_in[0];
    const int*   tgt  = (const int*)  d_in[1];
    const float* embs = (const float*)d_in[2];
    float* out = (float*)d_out;

    k_zero<<<NB / 256, 256>>>(out);
    dim3 grid(NBLK, CS);
    k_main<<<grid, 256>>>(pred, embs);
    k_fin<<<NB / 256, 256>>>(pred, tgt, embs, out);
}

// round 4
// speedup vs baseline: 5.1783x; 5.1783x over previous
#include <cuda_runtime.h>
#include <cuda_bf16.h>
#include <cstdint>
#include <cstddef>

#define NB 8192
#define NC 32000
#define ND 32

static constexpr int TM   = 128;              // rows per CTA
static constexpr int TN   = 128;              // classes per tile
static constexpr int GY   = 50;               // class splits
static constexpr int TPC  = NC / (GY * TN);   // 5 tiles per CTA
static constexpr int GX   = NB / TM;          // 64 row blocks
static constexpr int RPAD = 80;               // padded row bytes (64 real) -> conflict-free ldmatrix
static constexpr int BUFB = TN * RPAD;        // 10240 B per B buffer

#define Y_MIN (1.0f + 1e-6f)

__device__ float g_S[NB];                       // per-row sum of exp(-dist)
__device__ __nv_bfloat16 g_pred_bf[NB * ND];    // sign-folded pred (bf16)
__device__ __nv_bfloat16 g_emb_bf[NC * ND];     // class embeddings (bf16)

// ---------------- helpers -----------------------------------------------------
__device__ __forceinline__ uint32_t smem_u32(const void* p) {
    uint32_t r;
    asm("{ .reg .u64 t; cvta.to.shared.u64 t, %1; cvt.u32.u64 %0, t; }" : "=r"(r) : "l"(p));
    return r;
}
__device__ __forceinline__ void cp16(uint32_t dst, const void* src) {
    asm volatile("cp.async.cg.shared.global [%0], [%1], 16;" :: "r"(dst), "l"(src));
}
__device__ __forceinline__ void ldsm4(uint32_t& r0, uint32_t& r1, uint32_t& r2, uint32_t& r3,
                                      uint32_t a) {
    asm volatile("ldmatrix.sync.aligned.m8n8.x4.shared.b16 {%0,%1,%2,%3}, [%4];"
                 : "=r"(r0), "=r"(r1), "=r"(r2), "=r"(r3) : "r"(a));
}
__device__ __forceinline__ void mma16816(float* c, const uint32_t* a, uint32_t b0, uint32_t b1) {
    asm volatile(
        "mma.sync.aligned.m16n8k16.row.col.f32.bf16.bf16.f32 "
        "{%0,%1,%2,%3}, {%4,%5,%6,%7}, {%8,%9}, {%0,%1,%2,%3};"
        : "+f"(c[0]), "+f"(c[1]), "+f"(c[2]), "+f"(c[3])
        : "r"(a[0]), "r"(a[1]), "r"(a[2]), "r"(a[3]), "r"(b0), "r"(b1));
}
__device__ __forceinline__ float sqrt_approx(float x) {
    float r; asm("sqrt.approx.f32 %0, %1;" : "=f"(r) : "f"(x)); return r;
}
__device__ __forceinline__ float texp(float y) {   // exp(-arccosh(y)) = y - sqrt(y^2-1)
    y = fmaxf(y, Y_MIN);
    return y - sqrt_approx(fmaf(y, y, -1.0f));
}

// ---------------- prep kernels ------------------------------------------------
// pred -> bf16 with Lorentz sign folded (A[m][0]=p0, A[m][k>0]=-p_k); zeros accums.
__global__ void __launch_bounds__(256) k_prep(const float* __restrict__ pred,
                                              float* __restrict__ out) {
    int i = blockIdx.x * 256 + threadIdx.x;          // grid 512 -> i < 131072
    float2 v = reinterpret_cast<const float2*>(pred)[i];
    int k = (i * 2) & 31;
    float a = (k == 0) ? v.x : -v.x;
    reinterpret_cast<__nv_bfloat162*>(g_pred_bf)[i] = __floats2bfloat162_rn(a, -v.y);
    if (i < NB) g_S[i] = 0.0f;
    if (i == 0) out[0] = 0.0f;
}

__global__ void __launch_bounds__(256) k_cemb(const float* __restrict__ embs) {
    int i = blockIdx.x * 256 + threadIdx.x;          // grid 2000 -> i < 512000
    float2 v = reinterpret_cast<const float2*>(embs)[i];
    reinterpret_cast<__nv_bfloat162*>(g_emb_bf)[i] = __floats2bfloat162_rn(v.x, v.y);
}

// ---------------- main: mma.sync GEMM + fused exp(-arccosh) row sums ----------
__global__ void __launch_bounds__(256) k_main() {
    __shared__ __align__(16) char sA[TM * RPAD];        // 10240 B
    __shared__ __align__(16) char sB[2][TN * RPAD];     // 2 x 10240 B

    const int tid  = threadIdx.x;
    const int w    = tid >> 5;
    const int lane = tid & 31;

    const uint32_t a_s = smem_u32(sA);
    const uint32_t b_s = smem_u32(sB);

    const char* gA = reinterpret_cast<const char*>(g_pred_bf) + (size_t)blockIdx.x * TM * 64;
    const int cls_base = blockIdx.y * (TPC * TN);
    const char* gB0 = reinterpret_cast<const char*>(g_emb_bf) + (size_t)cls_base * 64;

    // ---- prologue: stage A and B tile 0 ----
#pragma unroll
    for (int i = 0; i < 2; i++) {
        int L = tid + i * 256;                 // 512 x 16B chunks each
        int r = L >> 2, c = L & 3;
        cp16(a_s + r * RPAD + c * 16, gA + r * 64 + c * 16);
        cp16(b_s + r * RPAD + c * 16, gB0 + r * 64 + c * 16);
    }
    asm volatile("cp.async.commit_group;" ::: "memory");
    asm volatile("cp.async.wait_group 0;" ::: "memory");
    __syncthreads();

    // ---- load A fragments once (rows w*16 .. w*16+15, K=32) ----
    // ldmatrix lane mapping: rA = row half by bit3, +16B col by bit4
    const int rA = (lane & 7) + ((lane >> 3) & 1) * 8;
    const int cA = (lane >> 4) & 1;
    uint32_t afrag[2][4];
    {
        uint32_t base = a_s + (w * 16 + rA) * RPAD + cA * 16;
        ldsm4(afrag[0][0], afrag[0][1], afrag[0][2], afrag[0][3], base);        // k 0..15
        ldsm4(afrag[1][0], afrag[1][1], afrag[1][2], afrag[1][3], base + 32);   // k 16..31
    }

    // B ldmatrix lane mapping: class half by bit4, +16B (k) by bit3
    const int rB = (lane & 7) + ((lane >> 4) & 1) * 8;
    const int cB = (lane >> 3) & 1;

    float acc0 = 0.0f, acc1 = 0.0f, acc2 = 0.0f, acc3 = 0.0f;

    int buf = 0;
#pragma unroll 1
    for (int t = 0; t < TPC; t++) {
        if (t + 1 < TPC) {
            const char* gB = reinterpret_cast<const char*>(g_emb_bf)
                           + (size_t)(cls_base + (t + 1) * TN) * 64;
            uint32_t dst = b_s + (buf ^ 1) * BUFB;
#pragma unroll
            for (int i = 0; i < 2; i++) {
                int L = tid + i * 256;
                int r = L >> 2, c = L & 3;
                cp16(dst + r * RPAD + c * 16, gB + r * 64 + c * 16);
            }
            asm volatile("cp.async.commit_group;" ::: "memory");
            asm volatile("cp.async.wait_group 1;" ::: "memory");
        } else {
            asm volatile("cp.async.wait_group 0;" ::: "memory");
        }
        __syncthreads();

        const uint32_t bbase = b_s + buf * BUFB + rB * RPAD + cB * 16;

#pragma unroll
        for (int g = 0; g < TN / 16; g++) {          // 8 groups of 16 classes
            float cL[4] = {0.f, 0.f, 0.f, 0.f};
            float cH[4] = {0.f, 0.f, 0.f, 0.f};
#pragma unroll
            for (int ks = 0; ks < 2; ks++) {
                uint32_t bL0, bL1, bH0, bH1;
                ldsm4(bL0, bL1, bH0, bH1, bbase + g * (16 * RPAD) + ks * 32);
                mma16816(cL, afrag[ks], bL0, bL1);
                mma16816(cH, afrag[ks], bH0, bH1);
            }
            acc0 += texp(cL[0]) + texp(cL[1]);
            acc1 += texp(cH[0]) + texp(cH[1]);
            acc2 += texp(cL[2]) + texp(cL[3]);
            acc3 += texp(cH[2]) + texp(cH[3]);
        }
        __syncthreads();     // all warps done with buf before it is overwritten
        buf ^= 1;
    }

    // rows: acc0+acc1 -> row lane/4 ; acc2+acc3 -> row lane/4 + 8 (within warp's 16 rows)
    float rlo = acc0 + acc1;
    float rhi = acc2 + acc3;
#pragma unroll
    for (int o = 1; o <= 2; o <<= 1) {
        rlo += __shfl_xor_sync(0xffffffffu, rlo, o);
        rhi += __shfl_xor_sync(0xffffffffu, rhi, o);
    }
    if ((lane & 3) == 0) {
        int rowbase = blockIdx.x * TM + w * 16 + (lane >> 2);
        atomicAdd(&g_S[rowbase],     rlo);
        atomicAdd(&g_S[rowbase + 8], rhi);
    }
}

// ---------------- finalize: target distance (exact fp32) + NLL mean -----------
__global__ void __launch_bounds__(256) k_fin(const float* __restrict__ pred,
                                             const int* __restrict__ tgt,
                                             const float* __restrict__ embs,
                                             float* __restrict__ out) {
    int r = blockIdx.x * 256 + threadIdx.x;
    int t = tgt[r];
    const float* pr = pred + r * ND;
    const float* ev = embs + (size_t)t * ND;

    float y = pr[0] * ev[0];
#pragma unroll
    for (int k = 1; k < ND; k++) y = fmaf(-pr[k], ev[k], y);
    y = fmaxf(y, Y_MIN);
    float nll = logf(g_S[r]) + acoshf(y);

#pragma unroll
    for (int o = 16; o; o >>= 1) nll += __shfl_down_sync(0xffffffffu, nll, o);

    __shared__ float sm[8];
    if ((threadIdx.x & 31) == 0) sm[threadIdx.x >> 5] = nll;
    __syncthreads();
    if (threadIdx.x == 0) {
        float s = 0.0f;
#pragma unroll
        for (int k = 0; k < 8; k++) s += sm[k];
        atomicAdd(out, s * (1.0f / NB));
    }
}

// ---------------- launch ------------------------------------------------------
extern "C" void kernel_launch(void* const* d_in, const int* in_sizes, int n_in,
                              void* d_out, int out_size) {
    const float* pred = (const float*)d_in[0];
    const int*   tgt  = (const int*)  d_in[1];
    const float* embs = (const float*)d_in[2];
    float* out = (float*)d_out;

    k_prep<<<(NB * ND / 2) / 256, 256>>>(pred, out);
    k_cemb<<<(NC * ND / 2) / 256, 256>>>(embs);
    k_main<<<dim3(GX, GY), 256>>>();
    k_fin<<<NB / 256, 256>>>(pred, tgt, embs, out);
}

// round 8
// speedup vs baseline: 5.4817x; 1.0586x over previous
#include <cuda_runtime.h>
#include <cuda_bf16.h>
#include <cstdint>
#include <cstddef>

#define NB 8192
#define NC 32000
#define ND 32

static constexpr int TM   = 128;              // rows per CTA
static constexpr int TN   = 128;              // classes per tile
static constexpr int GY   = 50;               // class splits
static constexpr int TPC  = NC / (GY * TN);   // 5 tiles per CTA
static constexpr int GX   = NB / TM;          // 64 row blocks
static constexpr int RPAD = 80;               // padded row bytes (64 real) -> conflict-free ldmatrix
static constexpr int BUFB = TN * RPAD;        // 10240 B per B buffer

#define Y_MIN (1.0f + 1e-6f)

__device__ float g_S[NB];                       // per-row sum of exp(-dist)
__device__ __nv_bfloat16 g_pred_bf[NB * ND];    // sign-folded pred (bf16)
__device__ __nv_bfloat16 g_emb_bf[NC * ND];     // class embeddings (bf16)

// ---------------- helpers -----------------------------------------------------
__device__ __forceinline__ uint32_t smem_u32(const void* p) {
    uint32_t r;
    asm("{ .reg .u64 t; cvta.to.shared.u64 t, %1; cvt.u32.u64 %0, t; }" : "=r"(r) : "l"(p));
    return r;
}
__device__ __forceinline__ void cp16(uint32_t dst, const void* src) {
    asm volatile("cp.async.cg.shared.global [%0], [%1], 16;" :: "r"(dst), "l"(src));
}
__device__ __forceinline__ void ldsm4(uint32_t& r0, uint32_t& r1, uint32_t& r2, uint32_t& r3,
                                      uint32_t a) {
    asm volatile("ldmatrix.sync.aligned.m8n8.x4.shared.b16 {%0,%1,%2,%3}, [%4];"
                 : "=r"(r0), "=r"(r1), "=r"(r2), "=r"(r3) : "r"(a));
}
__device__ __forceinline__ void mma16816(float* c, const uint32_t* a, uint32_t b0, uint32_t b1) {
    asm volatile(
        "mma.sync.aligned.m16n8k16.row.col.f32.bf16.bf16.f32 "
        "{%0,%1,%2,%3}, {%4,%5,%6,%7}, {%8,%9}, {%0,%1,%2,%3};"
        : "+f"(c[0]), "+f"(c[1]), "+f"(c[2]), "+f"(c[3])
        : "r"(a[0]), "r"(a[1]), "r"(a[2]), "r"(a[3]), "r"(b0), "r"(b1));
}
__device__ __forceinline__ float sqrt_approx(float x) {
    float r; asm("sqrt.approx.f32 %0, %1;" : "=f"(r) : "f"(x)); return r;
}
__device__ __forceinline__ float texp(float y) {   // exp(-arccosh(y)) = y - sqrt(y^2-1)
    y = fmaxf(y, Y_MIN);
    return y - sqrt_approx(fmaf(y, y, -1.0f));
}

// ---------------- prep kernels ------------------------------------------------
// pred -> bf16 with Lorentz sign folded (A[m][0]=p0, A[m][k>0]=-p_k); zeros accums.
__global__ void __launch_bounds__(256) k_prep(const float* __restrict__ pred,
                                              float* __restrict__ out) {
    int i = blockIdx.x * 256 + threadIdx.x;          // grid 512 -> i < 131072
    float2 v = reinterpret_cast<const float2*>(pred)[i];
    int k = (i * 2) & 31;
    float a = (k == 0) ? v.x : -v.x;
    reinterpret_cast<__nv_bfloat162*>(g_pred_bf)[i] = __floats2bfloat162_rn(a, -v.y);
    if (i < NB) g_S[i] = 0.0f;
    if (i == 0) out[0] = 0.0f;
}

__global__ void __launch_bounds__(256) k_cemb(const float* __restrict__ embs) {
    int i = blockIdx.x * 256 + threadIdx.x;          // grid 2000 -> i < 512000
    float2 v = reinterpret_cast<const float2*>(embs)[i];
    reinterpret_cast<__nv_bfloat162*>(g_emb_bf)[i] = __floats2bfloat162_rn(v.x, v.y);
}

// ---------------- main: mma.sync GEMM + fused exp(-arccosh) row sums ----------
__global__ void __launch_bounds__(256) k_main() {
    __shared__ __align__(16) char sA[TM * RPAD];        // 10240 B
    __shared__ __align__(16) char sB[2][TN * RPAD];     // 2 x 10240 B

    const int tid  = threadIdx.x;
    const int w    = tid >> 5;
    const int lane = tid & 31;

    const uint32_t a_s = smem_u32(sA);
    const uint32_t b_s = smem_u32(sB);

    const char* gA = reinterpret_cast<const char*>(g_pred_bf) + (size_t)blockIdx.x * TM * 64;
    const int cls_base = blockIdx.y * (TPC * TN);
    const char* gB0 = reinterpret_cast<const char*>(g_emb_bf) + (size_t)cls_base * 64;

    // ---- prologue: stage A and B tile 0 ----
#pragma unroll
    for (int i = 0; i < 2; i++) {
        int L = tid + i * 256;                 // 512 x 16B chunks each
        int r = L >> 2, c = L & 3;
        cp16(a_s + r * RPAD + c * 16, gA + r * 64 + c * 16);
        cp16(b_s + r * RPAD + c * 16, gB0 + r * 64 + c * 16);
    }
    asm volatile("cp.async.commit_group;" ::: "memory");
    asm volatile("cp.async.wait_group 0;" ::: "memory");
    __syncthreads();

    // ---- load A fragments once (rows w*16 .. w*16+15, K=32) ----
    const int rA = (lane & 7) + ((lane >> 3) & 1) * 8;
    const int cA = (lane >> 4) & 1;
    uint32_t afrag[2][4];
    {
        uint32_t base = a_s + (w * 16 + rA) * RPAD + cA * 16;
        ldsm4(afrag[0][0], afrag[0][1], afrag[0][2], afrag[0][3], base);        // k 0..15
        ldsm4(afrag[1][0], afrag[1][1], afrag[1][2], afrag[1][3], base + 32);   // k 16..31
    }

    // B ldmatrix lane mapping: class half by bit4, +16B (k) by bit3
    const int rB = (lane & 7) + ((lane >> 4) & 1) * 8;
    const int cB = (lane >> 3) & 1;

    float acc0 = 0.0f, acc1 = 0.0f, acc2 = 0.0f, acc3 = 0.0f;

    int buf = 0;
#pragma unroll 1
    for (int t = 0; t < TPC; t++) {
        if (t + 1 < TPC) {
            const char* gB = reinterpret_cast<const char*>(g_emb_bf)
                           + (size_t)(cls_base + (t + 1) * TN) * 64;
            uint32_t dst = b_s + (buf ^ 1) * BUFB;
#pragma unroll
            for (int i = 0; i < 2; i++) {
                int L = tid + i * 256;
                int r = L >> 2, c = L & 3;
                cp16(dst + r * RPAD + c * 16, gB + r * 64 + c * 16);
            }
            asm volatile("cp.async.commit_group;" ::: "memory");
            asm volatile("cp.async.wait_group 1;" ::: "memory");
        } else {
            asm volatile("cp.async.wait_group 0;" ::: "memory");
        }
        __syncthreads();

        const uint32_t bbase = b_s + buf * BUFB + rB * RPAD + cB * 16;

#pragma unroll
        for (int g = 0; g < TN / 16; g++) {          // 8 groups of 16 classes
            float cL[4] = {0.f, 0.f, 0.f, 0.f};
            float cH[4] = {0.f, 0.f, 0.f, 0.f};
#pragma unroll
            for (int ks = 0; ks < 2; ks++) {
                uint32_t bL0, bL1, bH0, bH1;
                ldsm4(bL0, bL1, bH0, bH1, bbase + g * (16 * RPAD) + ks * 32);
                mma16816(cL, afrag[ks], bL0, bL1);
                mma16816(cH, afrag[ks], bH0, bH1);
            }
            acc0 += texp(cL[0]) + texp(cL[1]);
            acc1 += texp(cH[0]) + texp(cH[1]);
            acc2 += texp(cL[2]) + texp(cL[3]);
            acc3 += texp(cH[2]) + texp(cH[3]);
        }
        __syncthreads();     // all warps done with buf before it is overwritten
        buf ^= 1;
    }

    // rows: acc0+acc1 -> row lane/4 ; acc2+acc3 -> row lane/4 + 8 (within warp's 16 rows)
    float rlo = acc0 + acc1;
    float rhi = acc2 + acc3;
#pragma unroll
    for (int o = 1; o <= 2; o <<= 1) {
        rlo += __shfl_xor_sync(0xffffffffu, rlo, o);
        rhi += __shfl_xor_sync(0xffffffffu, rhi, o);
    }
    if ((lane & 3) == 0) {
        int rowbase = blockIdx.x * TM + w * 16 + (lane >> 2);
        atomicAdd(&g_S[rowbase],     rlo);
        atomicAdd(&g_S[rowbase + 8], rhi);
    }
}

// ---------------- finalize: warp-per-row target distance + NLL mean -----------
// lane = dimension: coalesced 128B pred row + one 128B emb row per warp.
// ALL barriers are convergent (executed unconditionally by all 256 threads).
__global__ void __launch_bounds__(256) k_fin(const float* __restrict__ pred,
                                             const int* __restrict__ tgt,
                                             const float* __restrict__ embs,
                                             float* __restrict__ out) {
    __shared__ float sm[8];
    int r    = (blockIdx.x * 256 + threadIdx.x) >> 5;   // row 0..8191 (grid 1024)
    int lane = threadIdx.x & 31;

    int t = tgt[r];
    float p = pred[r * ND + lane];
    float e = __ldg(&embs[(size_t)t * ND + lane]);
    float term = (lane == 0) ? p * e : -p * e;
#pragma unroll
    for (int o = 16; o; o >>= 1) term += __shfl_xor_sync(0xffffffffu, term, o);

    // every lane has the full dot product now; lane 0 computes & stores nll
    if (lane == 0) {
        float y = fmaxf(term, Y_MIN);
        sm[threadIdx.x >> 5] = logf(g_S[r]) + acoshf(y);
    }
    __syncthreads();                         // convergent: all threads
    if (threadIdx.x == 0) {
        float s = 0.0f;
#pragma unroll
        for (int k = 0; k < 8; k++) s += sm[k];
        atomicAdd(out, s * (1.0f / NB));
    }
}

// ---------------- launch ------------------------------------------------------
extern "C" void kernel_launch(void* const* d_in, const int* in_sizes, int n_in,
                              void* d_out, int out_size) {
    const float* pred = (const float*)d_in[0];
    const int*   tgt  = (const int*)  d_in[1];
    const float* embs = (const float*)d_in[2];
    float* out = (float*)d_out;

    k_prep<<<(NB * ND / 2) / 256, 256>>>(pred, out);
    k_cemb<<<(NC * ND / 2) / 256, 256>>>(embs);
    k_main<<<dim3(GX, GY), 256>>>();
    k_fin<<<NB * 32 / 256, 256>>>(pred, tgt, embs, out);
}